// round 10
// baseline (speedup 1.0000x reference)
#include <cuda_runtime.h>
#include <cstdint>

// ============================================================================
// Problem constants
// ============================================================================
#define D_DIM 4096
#define BM 128
#define BN 128
#define BK 128                  // bytes of K per pipeline stage (= 128 k-values)
#define NSTAGE 3
#define KT_ITERS (D_DIM / BK)   // 32
#define THREADS 256

#define A_STAGE 16384           // 128 rows x 128B
#define B_STAGE 16384
#define STAGE_BYTES (A_STAGE + B_STAGE)   // 32 KB; 3 stages = 96 KB/CTA

// ============================================================================
// Scratch (device globals; no allocation allowed)
// ============================================================================
__device__ __align__(1024) signed char g_qx[(size_t)D_DIM * D_DIM]; // int8 activations
__device__ __align__(1024) signed char g_wq[(size_t)D_DIM * D_DIM]; // int8 weights
__device__ float g_sx[D_DIM];                                        // activation row scales

// ============================================================================
// PTX helpers — base ISA only
// ============================================================================
__device__ __forceinline__ uint32_t smem_u32(const void* p) {
    uint32_t a;
    asm("{ .reg .u64 t; cvta.to.shared.u64 t, %1; cvt.u32.u64 %0, t; }" : "=r"(a) : "l"(p));
    return a;
}

#define CP_ASYNC16(dst, src) \
    asm volatile("cp.async.cg.shared.global [%0], [%1], 16;" :: "r"(dst), "l"(src))
#define CP_COMMIT() asm volatile("cp.async.commit_group;" ::: "memory")
#define CP_WAIT1()  asm volatile("cp.async.wait_group 1;" ::: "memory")

#define LDM_X4(r, addr) \
    asm volatile("ldmatrix.sync.aligned.m8n8.x4.shared.b16 {%0,%1,%2,%3}, [%4];" \
                 : "=r"((r)[0]), "=r"((r)[1]), "=r"((r)[2]), "=r"((r)[3]) : "r"(addr))

#define MMA_S8(c, a, b0, b1) \
    asm volatile("mma.sync.aligned.m16n8k32.row.col.s32.s8.s8.s32 " \
                 "{%0,%1,%2,%3},{%4,%5,%6,%7},{%8,%9},{%0,%1,%2,%3};" \
                 : "+r"((c)[0]), "+r"((c)[1]), "+r"((c)[2]), "+r"((c)[3]) \
                 : "r"((a)[0]), "r"((a)[1]), "r"((a)[2]), "r"((a)[3]), "r"(b0), "r"(b1))

// SMEM tile: 128 rows x 128B. Every row starts at bank 0 (128B = 32 words), so
// swizzle 16B chunks by phys = ch ^ (row & 7): 8 consecutive rows map any fixed
// logical chunk to 8 distinct 16B columns -> conflict-free ldmatrix AND stores.
__device__ __forceinline__ uint32_t tile_off(int row, int chunk) {
    return (uint32_t)(row * 128 + ((chunk ^ (row & 7)) << 4));
}

// ============================================================================
// Kernel 1 (fused prep):
//   blocks [0,4096):    Hadamard-256 + per-row int4 quantize -> s8
//   blocks [4096,8192): weight int32 -> s8 (one weight row per block)
// Activation layout: elem i = lane*8 + j (strides 1,2,4 in-register; 8..128 shfl)
// ============================================================================
__global__ __launch_bounds__(512) void prep_kernel(
    const float* __restrict__ x, const int4* __restrict__ wi,
    signed char* __restrict__ qx, signed char* __restrict__ wq,
    float* __restrict__ sxv)
{
    if (blockIdx.x >= 4096) {
        int row = blockIdx.x - 4096;
        int t = threadIdx.x;
        const int4* wr = wi + (size_t)row * 1024 + t * 2;
        int4 v0 = wr[0], v1 = wr[1];
        uint32_t p0 = ((uint32_t)v0.x & 0xFF)        | (((uint32_t)v0.y & 0xFF) << 8)
                    | (((uint32_t)v0.z & 0xFF) << 16) | (((uint32_t)v0.w & 0xFF) << 24);
        uint32_t p1 = ((uint32_t)v1.x & 0xFF)        | (((uint32_t)v1.y & 0xFF) << 8)
                    | (((uint32_t)v1.z & 0xFF) << 16) | (((uint32_t)v1.w & 0xFF) << 24);
        *(uint2*)&wq[(size_t)row * D_DIM + t * 8] = make_uint2(p0, p1);
        return;
    }

    __shared__ float smax[16];
    int row  = blockIdx.x;
    int w    = threadIdx.x >> 5;
    int lane = threadIdx.x & 31;

    const float* xr = x + (size_t)row * D_DIM + w * 256 + lane * 8;
    float v[8];
    {
        float4 u0 = *(const float4*)xr;
        float4 u1 = *(const float4*)(xr + 4);
        v[0] = u0.x; v[1] = u0.y; v[2] = u0.z; v[3] = u0.w;
        v[4] = u1.x; v[5] = u1.y; v[6] = u1.z; v[7] = u1.w;
    }

    // strides 1,2,4 (j bits), in-register
#pragma unroll
    for (int b = 1; b < 8; b <<= 1) {
#pragma unroll
        for (int j = 0; j < 8; j++) {
            if (!(j & b)) {
                float a = v[j], c = v[j | b];
                v[j] = a + c; v[j | b] = a - c;
            }
        }
    }
    // strides 8..128 (lane bits), shfl
#pragma unroll
    for (int s = 1; s < 32; s <<= 1) {
#pragma unroll
        for (int j = 0; j < 8; j++) {
            float o = __shfl_xor_sync(0xFFFFFFFFu, v[j], s);
            v[j] = (lane & s) ? (o - v[j]) : (v[j] + o);
        }
    }
#pragma unroll
    for (int j = 0; j < 8; j++) v[j] *= 0.0625f;   // 1/sqrt(256)

    float mx = 0.0f;
#pragma unroll
    for (int j = 0; j < 8; j++) mx = fmaxf(mx, fabsf(v[j]));
#pragma unroll
    for (int s = 16; s; s >>= 1) mx = fmaxf(mx, __shfl_xor_sync(0xFFFFFFFFu, mx, s));
    if (lane == 0) smax[w] = mx;
    __syncthreads();
    float tot = smax[0];
#pragma unroll
    for (int i = 1; i < 16; i++) tot = fmaxf(tot, smax[i]);

    if (threadIdx.x == 0) sxv[row] = tot * (1.0f / 7.0f);
    float inv = 7.0f / tot;

    int qi[8];
#pragma unroll
    for (int j = 0; j < 8; j++) {
        float q = rintf(v[j] * inv);               // round-half-even == jnp.round
        q = fminf(fmaxf(q, -8.0f), 7.0f);
        qi[j] = (int)q;
    }
    uint32_t p0 = ((uint32_t)qi[0] & 0xFF)        | (((uint32_t)qi[1] & 0xFF) << 8)
                | (((uint32_t)qi[2] & 0xFF) << 16) | (((uint32_t)qi[3] & 0xFF) << 24);
    uint32_t p1 = ((uint32_t)qi[4] & 0xFF)        | (((uint32_t)qi[5] & 0xFF) << 8)
                | (((uint32_t)qi[6] & 0xFF) << 16) | (((uint32_t)qi[7] & 0xFF) << 24);
    *(uint2*)&qx[(size_t)row * D_DIM + w * 256 + lane * 8] = make_uint2(p0, p1);
}

// ============================================================================
// Kernel 2: int8 GEMM, tile 128x128, 256 threads (8 warps, 2Mx4N, warp 64x32),
// BK=128B stage, 3-stage cp.async pipeline (one sync per 4 k32-steps),
// 2 CTAs/SM, fused dequant epilogue.
// ============================================================================
__global__ __launch_bounds__(THREADS, 2) void gemm_kernel(
    const signed char* __restrict__ gA,
    const signed char* __restrict__ gB,
    const float* __restrict__ sx,
    const float* __restrict__ ws,
    const float* __restrict__ bias,
    float* __restrict__ out)
{
    extern __shared__ char smem[];
    uint32_t sbase = smem_u32(smem);
    const uint32_t sA0 = sbase;                       // NSTAGE x A_STAGE
    const uint32_t sB0 = sbase + NSTAGE * A_STAGE;    // NSTAGE x B_STAGE

    int tid  = threadIdx.x;
    int lane = tid & 31;
    int wid  = tid >> 5;
    int m0 = blockIdx.x * BM;
    int n0 = blockIdx.y * BN;
    int wm = wid & 1;           // 2 warps over M
    int wn = wid >> 1;          // 4 warps over N
    int Amb = wm * 64;
    int Bnb = wn * 32;
    int i8 = lane & 7, g = lane >> 3;

    int acc[4][4][4];
#pragma unroll
    for (int a = 0; a < 4; a++)
#pragma unroll
        for (int b = 0; b < 4; b++)
#pragma unroll
            for (int c = 0; c < 4; c++) acc[a][b][c] = 0;

    // loads: one 128B row per thread per stage. threads [0,128): A; [128,256): B.
    bool isB = tid >= 128;
    int lrow = tid & 127;
    const signed char* gsrc = (isB ? gB + (size_t)(n0 + lrow) * D_DIM
                                   : gA + (size_t)(m0 + lrow) * D_DIM);
    uint32_t sdst_base = (isB ? sB0 : sA0) + (uint32_t)lrow * 128;
    uint32_t soffs[8];
#pragma unroll
    for (int i = 0; i < 8; i++) soffs[i] = ((i ^ (lrow & 7)) << 4);

    auto load_stage = [&](int kt, int buf) {
        const signed char* src = gsrc + kt * BK;
        uint32_t dst = sdst_base + buf * STAGE_BYTES;   // A and B advance together
#pragma unroll
        for (int i = 0; i < 8; i++)
            CP_ASYNC16(dst + soffs[i], src + i * 16);
    };
    // note: stage buffers are interleaved as [A0 B0][A1 B1]... via STAGE_BYTES
    // stride with sB0 = sA0 + NSTAGE*A_STAGE; rewrite bases accordingly:
    // (sdst_base already includes sA0 or sB0; buf advances by STAGE_BYTES would
    // collide. Use per-matrix stage stride instead.)

    // precomputed ldmatrix offsets (stage-relative); chunk = ks*2 + bit, ks 0..3
    uint32_t aoffs[4][4], boffs[2][4];
#pragma unroll
    for (int mb = 0; mb < 4; mb++) {
        int row = Amb + mb * 16 + i8 + (g & 1) * 8;
#pragma unroll
        for (int ks = 0; ks < 4; ks++)
            aoffs[mb][ks] = tile_off(row, ks * 2 + (g >> 1));
    }
#pragma unroll
    for (int np = 0; np < 2; np++) {
        int row = Bnb + np * 16 + i8 + (g >> 1) * 8;
#pragma unroll
        for (int ks = 0; ks < 4; ks++)
            boffs[np][ks] = tile_off(row, ks * 2 + (g & 1));
    }

    // fix load_stage buffer stride: per-matrix stages are A_STAGE (=B_STAGE) apart
    auto load_stage2 = [&](int kt, int buf) {
        const signed char* src = gsrc + kt * BK;
        uint32_t dst = sdst_base + (uint32_t)buf * A_STAGE;
#pragma unroll
        for (int i = 0; i < 8; i++)
            CP_ASYNC16(dst + soffs[i], src + i * 16);
    };

    // prologue: fill 2 stages
#pragma unroll
    for (int s = 0; s < NSTAGE - 1; s++) {
        load_stage2(s, s);
        CP_COMMIT();
    }

    int buf = 0;          // buffer holding stage kt
    int lbuf = NSTAGE - 1; // buffer to load next
    for (int kt = 0; kt < KT_ITERS; kt++) {
        CP_WAIT1();           // stage kt resident (1 group still in flight)
        __syncthreads();

        int ldkt = kt + NSTAGE - 1;
        if (ldkt < KT_ITERS) load_stage2(ldkt, lbuf);
        CP_COMMIT();
        if (++lbuf == NSTAGE) lbuf = 0;

        uint32_t sA = sA0 + (uint32_t)buf * A_STAGE;
        uint32_t sB = sB0 + (uint32_t)buf * B_STAGE;
        if (++buf == NSTAGE) buf = 0;

#pragma unroll
        for (int ks = 0; ks < 4; ks++) {          // four k32 steps per stage
            uint32_t a[4][4], b[2][4];
#pragma unroll
            for (int mb = 0; mb < 4; mb++) LDM_X4(a[mb], sA + aoffs[mb][ks]);
#pragma unroll
            for (int np = 0; np < 2; np++) LDM_X4(b[np], sB + boffs[np][ks]);
#pragma unroll
            for (int mb = 0; mb < 4; mb++)
#pragma unroll
                for (int nb = 0; nb < 4; nb++)
                    MMA_S8(acc[mb][nb], a[mb],
                           b[nb >> 1][(nb & 1) * 2], b[nb >> 1][(nb & 1) * 2 + 1]);
        }
    }

    // ---- epilogue: dequant + bias, float2 stores ----
#pragma unroll
    for (int mb = 0; mb < 4; mb++) {
        int r0 = m0 + Amb + mb * 16 + (lane >> 2);
        float sx0 = sx[r0], sx1 = sx[r0 + 8];
#pragma unroll
        for (int nb = 0; nb < 4; nb++) {
            int c0 = n0 + Bnb + nb * 8 + (lane & 3) * 2;
            float w0 = ws[c0],  w1 = ws[c0 + 1];
            float f0 = bias[c0], f1 = bias[c0 + 1];
            float2 v0, v1;
            v0.x = (float)acc[mb][nb][0] * sx0 * w0 + f0;
            v0.y = (float)acc[mb][nb][1] * sx0 * w1 + f1;
            v1.x = (float)acc[mb][nb][2] * sx1 * w0 + f0;
            v1.y = (float)acc[mb][nb][3] * sx1 * w1 + f1;
            *(float2*)&out[(size_t)r0 * D_DIM + c0]       = v0;
            *(float2*)&out[(size_t)(r0 + 8) * D_DIM + c0] = v1;
        }
    }
}

// ============================================================================
// Host launcher
// ============================================================================
extern "C" void kernel_launch(void* const* d_in, const int* in_sizes, int n_in,
                              void* d_out, int out_size)
{
    const float* x    = (const float*)d_in[0];
    const int*   wi   = (const int*)  d_in[1];
    const float* wsc  = (const float*)d_in[2];
    const float* bias = (const float*)d_in[3];
    float*       out  = (float*)d_out;

    void *pqx = nullptr, *pwq = nullptr, *psx = nullptr;
    cudaGetSymbolAddress(&pqx, g_qx);
    cudaGetSymbolAddress(&pwq, g_wq);
    cudaGetSymbolAddress(&psx, g_sx);

    static bool attr_set = false;
    if (!attr_set) {
        cudaFuncSetAttribute(gemm_kernel, cudaFuncAttributeMaxDynamicSharedMemorySize,
                             NSTAGE * STAGE_BYTES);
        attr_set = true;
    }

    // 1) fused prep
    prep_kernel<<<8192, 512>>>(x, (const int4*)wi,
                               (signed char*)pqx, (signed char*)pwq, (float*)psx);

    // 2) s8 GEMM + fused dequant
    dim3 grid(D_DIM / BM, D_DIM / BN, 1);
    gemm_kernel<<<grid, THREADS, NSTAGE * STAGE_BYTES>>>(
        (const signed char*)pqx, (const signed char*)pwq,
        (const float*)psx, wsc, bias, out);
}

// round 11
// speedup vs baseline: 1.1337x; 1.1337x over previous
#include <cuda_runtime.h>
#include <cstdint>

// ============================================================================
// Problem constants
// ============================================================================
#define D_DIM 4096
#define BM 128
#define BN 128
#define BK 128                  // bytes of K per pipeline stage (= 128 k-values)
#define NSTAGE 3
#define KT_ITERS (D_DIM / BK)   // 32
#define THREADS 256

#define A_STAGE 16384           // 128 rows x 128B
#define B_STAGE 16384
#define STAGE_BYTES (A_STAGE + B_STAGE)   // 32 KB; 3 stages = 96 KB/CTA

// ============================================================================
// Scratch (device globals; no allocation allowed)
// ============================================================================
__device__ __align__(1024) signed char g_qx[(size_t)D_DIM * D_DIM]; // int8 activations
__device__ __align__(1024) signed char g_wq[(size_t)D_DIM * D_DIM]; // int8 weights
__device__ float g_sx[D_DIM];                                        // activation row scales

// ============================================================================
// PTX helpers — base ISA only
// ============================================================================
__device__ __forceinline__ uint32_t smem_u32(const void* p) {
    uint32_t a;
    asm("{ .reg .u64 t; cvta.to.shared.u64 t, %1; cvt.u32.u64 %0, t; }" : "=r"(a) : "l"(p));
    return a;
}

#define CP_ASYNC16(dst, src) \
    asm volatile("cp.async.cg.shared.global [%0], [%1], 16;" :: "r"(dst), "l"(src))
#define CP_COMMIT() asm volatile("cp.async.commit_group;" ::: "memory")
#define CP_WAIT1()  asm volatile("cp.async.wait_group 1;" ::: "memory")

#define LDM_X4(r, addr) \
    asm volatile("ldmatrix.sync.aligned.m8n8.x4.shared.b16 {%0,%1,%2,%3}, [%4];" \
                 : "=r"((r)[0]), "=r"((r)[1]), "=r"((r)[2]), "=r"((r)[3]) : "r"(addr))

#define MMA_S8(c, a, b0, b1) \
    asm volatile("mma.sync.aligned.m16n8k32.row.col.s32.s8.s8.s32 " \
                 "{%0,%1,%2,%3},{%4,%5,%6,%7},{%8,%9},{%0,%1,%2,%3};" \
                 : "+r"((c)[0]), "+r"((c)[1]), "+r"((c)[2]), "+r"((c)[3]) \
                 : "r"((a)[0]), "r"((a)[1]), "r"((a)[2]), "r"((a)[3]), "r"(b0), "r"(b1))

// SMEM tile: 128 rows x 128B. Every row starts at bank 0, so swizzle 16B chunks
// by phys = ch ^ (row & 7): any 8 consecutive rows map a fixed logical chunk to
// 8 distinct 16B columns -> conflict-free for ldmatrix reads and full-row stores.
__device__ __forceinline__ uint32_t tile_off(int row, int chunk) {
    return (uint32_t)(row * 128 + ((chunk ^ (row & 7)) << 4));
}

// ============================================================================
// Kernel 1 (fused prep):
//   blocks [0,4096):    Hadamard-256 + per-row int4 quantize -> s8
//   blocks [4096,8192): weight int32 -> s8 (one weight row per block)
// ============================================================================
__global__ __launch_bounds__(512) void prep_kernel(
    const float* __restrict__ x, const int4* __restrict__ wi,
    signed char* __restrict__ qx, signed char* __restrict__ wq,
    float* __restrict__ sxv)
{
    if (blockIdx.x >= 4096) {
        int row = blockIdx.x - 4096;
        int t = threadIdx.x;
        const int4* wr = wi + (size_t)row * 1024 + t * 2;
        int4 v0 = wr[0], v1 = wr[1];
        uint32_t p0 = ((uint32_t)v0.x & 0xFF)        | (((uint32_t)v0.y & 0xFF) << 8)
                    | (((uint32_t)v0.z & 0xFF) << 16) | (((uint32_t)v0.w & 0xFF) << 24);
        uint32_t p1 = ((uint32_t)v1.x & 0xFF)        | (((uint32_t)v1.y & 0xFF) << 8)
                    | (((uint32_t)v1.z & 0xFF) << 16) | (((uint32_t)v1.w & 0xFF) << 24);
        *(uint2*)&wq[(size_t)row * D_DIM + t * 8] = make_uint2(p0, p1);
        return;
    }

    __shared__ float smax[16];
    int row  = blockIdx.x;
    int w    = threadIdx.x >> 5;
    int lane = threadIdx.x & 31;

    const float* xr = x + (size_t)row * D_DIM + w * 256 + lane * 8;
    float v[8];
    {
        float4 u0 = *(const float4*)xr;
        float4 u1 = *(const float4*)(xr + 4);
        v[0] = u0.x; v[1] = u0.y; v[2] = u0.z; v[3] = u0.w;
        v[4] = u1.x; v[5] = u1.y; v[6] = u1.z; v[7] = u1.w;
    }

    // strides 1,2,4 (j bits), in-register
#pragma unroll
    for (int b = 1; b < 8; b <<= 1) {
#pragma unroll
        for (int j = 0; j < 8; j++) {
            if (!(j & b)) {
                float a = v[j], c = v[j | b];
                v[j] = a + c; v[j | b] = a - c;
            }
        }
    }
    // strides 8..128 (lane bits), shfl
#pragma unroll
    for (int s = 1; s < 32; s <<= 1) {
#pragma unroll
        for (int j = 0; j < 8; j++) {
            float o = __shfl_xor_sync(0xFFFFFFFFu, v[j], s);
            v[j] = (lane & s) ? (o - v[j]) : (v[j] + o);
        }
    }
#pragma unroll
    for (int j = 0; j < 8; j++) v[j] *= 0.0625f;   // 1/sqrt(256)

    float mx = 0.0f;
#pragma unroll
    for (int j = 0; j < 8; j++) mx = fmaxf(mx, fabsf(v[j]));
#pragma unroll
    for (int s = 16; s; s >>= 1) mx = fmaxf(mx, __shfl_xor_sync(0xFFFFFFFFu, mx, s));
    if (lane == 0) smax[w] = mx;
    __syncthreads();
    float tot = smax[0];
#pragma unroll
    for (int i = 1; i < 16; i++) tot = fmaxf(tot, smax[i]);

    if (threadIdx.x == 0) sxv[row] = tot * (1.0f / 7.0f);
    float inv = 7.0f / tot;

    int qi[8];
#pragma unroll
    for (int j = 0; j < 8; j++) {
        float q = rintf(v[j] * inv);               // round-half-even == jnp.round
        q = fminf(fmaxf(q, -8.0f), 7.0f);
        qi[j] = (int)q;
    }
    uint32_t p0 = ((uint32_t)qi[0] & 0xFF)        | (((uint32_t)qi[1] & 0xFF) << 8)
                | (((uint32_t)qi[2] & 0xFF) << 16) | (((uint32_t)qi[3] & 0xFF) << 24);
    uint32_t p1 = ((uint32_t)qi[4] & 0xFF)        | (((uint32_t)qi[5] & 0xFF) << 8)
                | (((uint32_t)qi[6] & 0xFF) << 16) | (((uint32_t)qi[7] & 0xFF) << 24);
    *(uint2*)&qx[(size_t)row * D_DIM + w * 256 + lane * 8] = make_uint2(p0, p1);
}

// ============================================================================
// Kernel 2: int8 GEMM, tile 128x128, 256 threads (8 warps, 2Mx4N, warp 64x32),
// BK=128B stage, 3-stage cp.async pipeline (one sync per 4 k32-steps),
// 2 CTAs/SM, COALESCED loads (8 threads cover one 128B row), fused dequant.
// ============================================================================
__global__ __launch_bounds__(THREADS, 2) void gemm_kernel(
    const signed char* __restrict__ gA,
    const signed char* __restrict__ gB,
    const float* __restrict__ sx,
    const float* __restrict__ ws,
    const float* __restrict__ bias,
    float* __restrict__ out)
{
    extern __shared__ char smem[];
    uint32_t sbase = smem_u32(smem);
    const uint32_t sA0 = sbase;                       // NSTAGE x A_STAGE
    const uint32_t sB0 = sbase + NSTAGE * A_STAGE;    // NSTAGE x B_STAGE

    int tid  = threadIdx.x;
    int lane = tid & 31;
    int wid  = tid >> 5;
    int m0 = blockIdx.x * BM;
    int n0 = blockIdx.y * BN;
    int wm = wid & 1;           // 2 warps over M
    int wn = wid >> 1;          // 4 warps over N
    int Amb = wm * 64;
    int Bnb = wn * 32;
    int i8 = lane & 7, g = lane >> 3;

    int acc[4][4][4];
#pragma unroll
    for (int a = 0; a < 4; a++)
#pragma unroll
        for (int b = 0; b < 4; b++)
#pragma unroll
            for (int c = 0; c < 4; c++) acc[a][b][c] = 0;

    // Coalesced loads: thread -> (row = tid>>3, chunk = tid&7); 8 consecutive
    // threads cover one row's 128B contiguously. 4 row-strided repeats (rows
    // +0/+32/+64/+96) x {A,B} = 8 cp.async of 16B per thread per stage.
    int lrow = tid >> 3, lch = tid & 7;
    const size_t gRstride = (size_t)32 * D_DIM;
    const signed char* gAp = gA + (size_t)(m0 + lrow) * D_DIM + lch * 16;
    const signed char* gBp = gB + (size_t)(n0 + lrow) * D_DIM + lch * 16;
    uint32_t soff = (uint32_t)lrow * 128 + ((lch ^ (lrow & 7)) << 4);

    auto load_stage = [&](int kt, int buf) {
        const int kb = kt * BK;
        uint32_t dA = sA0 + (uint32_t)buf * A_STAGE + soff;
        uint32_t dB = sB0 + (uint32_t)buf * B_STAGE + soff;
#pragma unroll
        for (int r = 0; r < 4; r++) {
            CP_ASYNC16(dA + r * 4096, gAp + kb + r * gRstride);
            CP_ASYNC16(dB + r * 4096, gBp + kb + r * gRstride);
        }
    };

    // precomputed ldmatrix offsets (stage-relative); chunk = ks*2 + bit, ks 0..3
    uint32_t aoffs[4][4], boffs[2][4];
#pragma unroll
    for (int mb = 0; mb < 4; mb++) {
        int row = Amb + mb * 16 + i8 + (g & 1) * 8;
#pragma unroll
        for (int ks = 0; ks < 4; ks++)
            aoffs[mb][ks] = tile_off(row, ks * 2 + (g >> 1));
    }
#pragma unroll
    for (int np = 0; np < 2; np++) {
        int row = Bnb + np * 16 + i8 + (g >> 1) * 8;
#pragma unroll
        for (int ks = 0; ks < 4; ks++)
            boffs[np][ks] = tile_off(row, ks * 2 + (g & 1));
    }

    // prologue: fill 2 stages
#pragma unroll
    for (int s = 0; s < NSTAGE - 1; s++) {
        load_stage(s, s);
        CP_COMMIT();
    }

    int buf = 0;            // buffer holding stage kt
    int lbuf = NSTAGE - 1;  // buffer to load next
    for (int kt = 0; kt < KT_ITERS; kt++) {
        CP_WAIT1();         // stage kt resident (<=1 group still in flight)
        __syncthreads();

        int ldkt = kt + NSTAGE - 1;
        if (ldkt < KT_ITERS) load_stage(ldkt, lbuf);
        CP_COMMIT();
        if (++lbuf == NSTAGE) lbuf = 0;

        uint32_t sA = sA0 + (uint32_t)buf * A_STAGE;
        uint32_t sB = sB0 + (uint32_t)buf * B_STAGE;
        if (++buf == NSTAGE) buf = 0;

#pragma unroll
        for (int ks = 0; ks < 4; ks++) {          // four k32 steps per stage
            uint32_t a[4][4], b[2][4];
#pragma unroll
            for (int mb = 0; mb < 4; mb++) LDM_X4(a[mb], sA + aoffs[mb][ks]);
#pragma unroll
            for (int np = 0; np < 2; np++) LDM_X4(b[np], sB + boffs[np][ks]);
#pragma unroll
            for (int mb = 0; mb < 4; mb++)
#pragma unroll
                for (int nb = 0; nb < 4; nb++)
                    MMA_S8(acc[mb][nb], a[mb],
                           b[nb >> 1][(nb & 1) * 2], b[nb >> 1][(nb & 1) * 2 + 1]);
        }
    }

    // ---- epilogue: dequant + bias, float2 stores ----
#pragma unroll
    for (int mb = 0; mb < 4; mb++) {
        int r0 = m0 + Amb + mb * 16 + (lane >> 2);
        float sx0 = sx[r0], sx1 = sx[r0 + 8];
#pragma unroll
        for (int nb = 0; nb < 4; nb++) {
            int c0 = n0 + Bnb + nb * 8 + (lane & 3) * 2;
            float w0 = ws[c0],  w1 = ws[c0 + 1];
            float f0 = bias[c0], f1 = bias[c0 + 1];
            float2 v0, v1;
            v0.x = (float)acc[mb][nb][0] * sx0 * w0 + f0;
            v0.y = (float)acc[mb][nb][1] * sx0 * w1 + f1;
            v1.x = (float)acc[mb][nb][2] * sx1 * w0 + f0;
            v1.y = (float)acc[mb][nb][3] * sx1 * w1 + f1;
            *(float2*)&out[(size_t)r0 * D_DIM + c0]       = v0;
            *(float2*)&out[(size_t)(r0 + 8) * D_DIM + c0] = v1;
        }
    }
}

// ============================================================================
// Host launcher
// ============================================================================
extern "C" void kernel_launch(void* const* d_in, const int* in_sizes, int n_in,
                              void* d_out, int out_size)
{
    const float* x    = (const float*)d_in[0];
    const int*   wi   = (const int*)  d_in[1];
    const float* wsc  = (const float*)d_in[2];
    const float* bias = (const float*)d_in[3];
    float*       out  = (float*)d_out;

    void *pqx = nullptr, *pwq = nullptr, *psx = nullptr;
    cudaGetSymbolAddress(&pqx, g_qx);
    cudaGetSymbolAddress(&pwq, g_wq);
    cudaGetSymbolAddress(&psx, g_sx);

    static bool attr_set = false;
    if (!attr_set) {
        cudaFuncSetAttribute(gemm_kernel, cudaFuncAttributeMaxDynamicSharedMemorySize,
                             NSTAGE * STAGE_BYTES);
        attr_set = true;
    }

    // 1) fused prep
    prep_kernel<<<8192, 512>>>(x, (const int4*)wi,
                               (signed char*)pqx, (signed char*)pwq, (float*)psx);

    // 2) s8 GEMM + fused dequant
    dim3 grid(D_DIM / BM, D_DIM / BN, 1);
    gemm_kernel<<<grid, THREADS, NSTAGE * STAGE_BYTES>>>(
        (const signed char*)pqx, (const signed char*)pwq,
        (const float*)psx, wsc, bias, out);
}

// round 14
// speedup vs baseline: 1.1381x; 1.0039x over previous
#include <cuda_runtime.h>
#include <cstdint>

// ============================================================================
// Problem constants
// ============================================================================
#define D_DIM 4096
#define BM 128
#define BN 128
#define BK 128                  // bytes of K per pipeline stage (= 128 k-values)
#define NSTAGE 3
#define KT_ITERS (D_DIM / BK)   // 32
#define THREADS 256

#define A_STAGE 16384           // 128 rows x 128B
#define B_STAGE 16384
#define STAGE_BYTES (A_STAGE + B_STAGE)   // 32 KB; 3 stages = 96 KB/CTA

// ============================================================================
// Scratch (device globals; no allocation allowed)
// ============================================================================
__device__ __align__(1024) signed char g_qx[(size_t)D_DIM * D_DIM]; // int8 activations
__device__ __align__(1024) signed char g_wq[(size_t)D_DIM * D_DIM]; // int8 weights
__device__ float g_sx[D_DIM];                                        // activation row scales

// ============================================================================
// PTX helpers — base ISA only
// ============================================================================
__device__ __forceinline__ uint32_t smem_u32(const void* p) {
    uint32_t a;
    asm("{ .reg .u64 t; cvta.to.shared.u64 t, %1; cvt.u32.u64 %0, t; }" : "=r"(a) : "l"(p));
    return a;
}

#define CP_ASYNC16(dst, src) \
    asm volatile("cp.async.cg.shared.global [%0], [%1], 16;" :: "r"(dst), "l"(src))
#define CP_COMMIT() asm volatile("cp.async.commit_group;" ::: "memory")
#define CP_WAIT1()  asm volatile("cp.async.wait_group 1;" ::: "memory")

#define LDM_X4(r, addr) \
    asm volatile("ldmatrix.sync.aligned.m8n8.x4.shared.b16 {%0,%1,%2,%3}, [%4];" \
                 : "=r"((r)[0]), "=r"((r)[1]), "=r"((r)[2]), "=r"((r)[3]) : "r"(addr))

#define MMA_S8(c, a, b0, b1) \
    asm volatile("mma.sync.aligned.m16n8k32.row.col.s32.s8.s8.s32 " \
                 "{%0,%1,%2,%3},{%4,%5,%6,%7},{%8,%9},{%0,%1,%2,%3};" \
                 : "+r"((c)[0]), "+r"((c)[1]), "+r"((c)[2]), "+r"((c)[3]) \
                 : "r"((a)[0]), "r"((a)[1]), "r"((a)[2]), "r"((a)[3]), "r"(b0), "r"(b1))

// SMEM tile: 128 rows x 128B. Every row starts at bank 0, so swizzle 16B chunks
// by phys = ch ^ (row & 7): any 8 consecutive rows map a fixed logical chunk to
// 8 distinct 16B columns -> conflict-free for ldmatrix reads and full-row stores.
__device__ __forceinline__ uint32_t tile_off(int row, int chunk) {
    return (uint32_t)(row * 128 + ((chunk ^ (row & 7)) << 4));
}

// ============================================================================
// Kernel 1 (fused prep), 256 threads/block:
//   blocks [0,4096):    Hadamard-256 + per-row int4 quantize -> s8.
//                       8 warps; warp w runs TWO independent 256-FWHT streams
//                       (segments 2w and 2w+1) for 2x ILP on the shfl chains.
//   blocks [4096,8192): weight int32 -> s8, one row per block, 4 int4/thread.
// Element layout within a segment: i = lane*8 + j (strides 1,2,4 in-register;
// 8..128 via shfl_xor). Sylvester FWHT is stride-order invariant.
// ============================================================================
__global__ __launch_bounds__(256) void prep_kernel(
    const float* __restrict__ x, const int4* __restrict__ wi,
    signed char* __restrict__ qx, signed char* __restrict__ wq,
    float* __restrict__ sxv)
{
    int tid = threadIdx.x;
    if (blockIdx.x >= 4096) {
        // ---- weight row -> s8: 4096 ints = 1024 int4; 256 threads x 4 int4 ----
        int row = blockIdx.x - 4096;
        const int4* wr = wi + (size_t)row * 1024 + tid * 4;
        int4 v0 = wr[0], v1 = wr[1], v2 = wr[2], v3 = wr[3];   // front-batched
        uint32_t p0 = ((uint32_t)v0.x & 0xFF)        | (((uint32_t)v0.y & 0xFF) << 8)
                    | (((uint32_t)v0.z & 0xFF) << 16) | (((uint32_t)v0.w & 0xFF) << 24);
        uint32_t p1 = ((uint32_t)v1.x & 0xFF)        | (((uint32_t)v1.y & 0xFF) << 8)
                    | (((uint32_t)v1.z & 0xFF) << 16) | (((uint32_t)v1.w & 0xFF) << 24);
        uint32_t p2 = ((uint32_t)v2.x & 0xFF)        | (((uint32_t)v2.y & 0xFF) << 8)
                    | (((uint32_t)v2.z & 0xFF) << 16) | (((uint32_t)v2.w & 0xFF) << 24);
        uint32_t p3 = ((uint32_t)v3.x & 0xFF)        | (((uint32_t)v3.y & 0xFF) << 8)
                    | (((uint32_t)v3.z & 0xFF) << 16) | (((uint32_t)v3.w & 0xFF) << 24);
        *(uint4*)&wq[(size_t)row * D_DIM + tid * 16] = make_uint4(p0, p1, p2, p3);
        return;
    }

    // ---- Hadamard + quantize: one x-row per block; warp w -> segments 2w,2w+1
    __shared__ float smax[8];
    int row  = blockIdx.x;
    int w    = tid >> 5;
    int lane = tid & 31;

    const float* xr0 = x + (size_t)row * D_DIM + (2 * w)     * 256 + lane * 8;
    const float* xr1 = x + (size_t)row * D_DIM + (2 * w + 1) * 256 + lane * 8;
    float va[8], vb[8];
    {
        float4 a0 = *(const float4*)xr0;
        float4 a1 = *(const float4*)(xr0 + 4);
        float4 b0 = *(const float4*)xr1;
        float4 b1 = *(const float4*)(xr1 + 4);
        va[0] = a0.x; va[1] = a0.y; va[2] = a0.z; va[3] = a0.w;
        va[4] = a1.x; va[5] = a1.y; va[6] = a1.z; va[7] = a1.w;
        vb[0] = b0.x; vb[1] = b0.y; vb[2] = b0.z; vb[3] = b0.w;
        vb[4] = b1.x; vb[5] = b1.y; vb[6] = b1.z; vb[7] = b1.w;
    }

    // strides 1,2,4 (j bits), in-register — two independent streams
#pragma unroll
    for (int b = 1; b < 8; b <<= 1) {
#pragma unroll
        for (int j = 0; j < 8; j++) {
            if (!(j & b)) {
                float t0 = va[j], t1 = va[j | b];
                va[j] = t0 + t1; va[j | b] = t0 - t1;
                float u0 = vb[j], u1 = vb[j | b];
                vb[j] = u0 + u1; vb[j | b] = u0 - u1;
            }
        }
    }
    // strides 8..128 (lane bits), shfl — two chains interleaved for ILP
#pragma unroll
    for (int s = 1; s < 32; s <<= 1) {
#pragma unroll
        for (int j = 0; j < 8; j++) {
            float oa = __shfl_xor_sync(0xFFFFFFFFu, va[j], s);
            float ob = __shfl_xor_sync(0xFFFFFFFFu, vb[j], s);
            va[j] = (lane & s) ? (oa - va[j]) : (va[j] + oa);
            vb[j] = (lane & s) ? (ob - vb[j]) : (vb[j] + ob);
        }
    }
#pragma unroll
    for (int j = 0; j < 8; j++) { va[j] *= 0.0625f; vb[j] *= 0.0625f; }

    float mx = 0.0f;
#pragma unroll
    for (int j = 0; j < 8; j++)
        mx = fmaxf(mx, fmaxf(fabsf(va[j]), fabsf(vb[j])));
#pragma unroll
    for (int s = 16; s; s >>= 1) mx = fmaxf(mx, __shfl_xor_sync(0xFFFFFFFFu, mx, s));
    if (lane == 0) smax[w] = mx;
    __syncthreads();
    float tot = smax[0];
#pragma unroll
    for (int i = 1; i < 8; i++) tot = fmaxf(tot, smax[i]);

    if (tid == 0) sxv[row] = tot * (1.0f / 7.0f);
    float inv = 7.0f / tot;

    int qa[8], qb[8];
#pragma unroll
    for (int j = 0; j < 8; j++) {
        float q0 = rintf(va[j] * inv);             // round-half-even == jnp.round
        q0 = fminf(fmaxf(q0, -8.0f), 7.0f);
        qa[j] = (int)q0;
        float q1 = rintf(vb[j] * inv);
        q1 = fminf(fmaxf(q1, -8.0f), 7.0f);
        qb[j] = (int)q1;
    }
    uint32_t a0 = ((uint32_t)qa[0] & 0xFF)        | (((uint32_t)qa[1] & 0xFF) << 8)
                | (((uint32_t)qa[2] & 0xFF) << 16) | (((uint32_t)qa[3] & 0xFF) << 24);
    uint32_t a1 = ((uint32_t)qa[4] & 0xFF)        | (((uint32_t)qa[5] & 0xFF) << 8)
                | (((uint32_t)qa[6] & 0xFF) << 16) | (((uint32_t)qa[7] & 0xFF) << 24);
    uint32_t b0 = ((uint32_t)qb[0] & 0xFF)        | (((uint32_t)qb[1] & 0xFF) << 8)
                | (((uint32_t)qb[2] & 0xFF) << 16) | (((uint32_t)qb[3] & 0xFF) << 24);
    uint32_t b1 = ((uint32_t)qb[4] & 0xFF)        | (((uint32_t)qb[5] & 0xFF) << 8)
                | (((uint32_t)qb[6] & 0xFF) << 16) | (((uint32_t)qb[7] & 0xFF) << 24);
    size_t base = (size_t)row * D_DIM;
    *(uint2*)&qx[base + (2 * w)     * 256 + lane * 8] = make_uint2(a0, a1);
    *(uint2*)&qx[base + (2 * w + 1) * 256 + lane * 8] = make_uint2(b0, b1);
}

// ============================================================================
// Kernel 2: int8 GEMM — UNCHANGED from R11 (916.8us, tensor 94.6%).
// Tile 128x128, 256 threads (8 warps, 2Mx4N, warp 64x32), BK=128B stage,
// 3-stage cp.async pipeline, 2 CTAs/SM, coalesced loads, fused dequant.
// ============================================================================
__global__ __launch_bounds__(THREADS, 2) void gemm_kernel(
    const signed char* __restrict__ gA,
    const signed char* __restrict__ gB,
    const float* __restrict__ sx,
    const float* __restrict__ ws,
    const float* __restrict__ bias,
    float* __restrict__ out)
{
    extern __shared__ char smem[];
    uint32_t sbase = smem_u32(smem);
    const uint32_t sA0 = sbase;                       // NSTAGE x A_STAGE
    const uint32_t sB0 = sbase + NSTAGE * A_STAGE;    // NSTAGE x B_STAGE

    int tid  = threadIdx.x;
    int lane = tid & 31;
    int wid  = tid >> 5;
    int m0 = blockIdx.x * BM;
    int n0 = blockIdx.y * BN;
    int wm = wid & 1;           // 2 warps over M
    int wn = wid >> 1;          // 4 warps over N
    int Amb = wm * 64;
    int Bnb = wn * 32;
    int i8 = lane & 7, g = lane >> 3;

    int acc[4][4][4];
#pragma unroll
    for (int a = 0; a < 4; a++)
#pragma unroll
        for (int b = 0; b < 4; b++)
#pragma unroll
            for (int c = 0; c < 4; c++) acc[a][b][c] = 0;

    // Coalesced loads: thread -> (row = tid>>3, chunk = tid&7); 8 consecutive
    // threads cover one row's 128B contiguously. 4 row-strided repeats x {A,B}.
    int lrow = tid >> 3, lch = tid & 7;
    const size_t gRstride = (size_t)32 * D_DIM;
    const signed char* gAp = gA + (size_t)(m0 + lrow) * D_DIM + lch * 16;
    const signed char* gBp = gB + (size_t)(n0 + lrow) * D_DIM + lch * 16;
    uint32_t soff = (uint32_t)lrow * 128 + ((lch ^ (lrow & 7)) << 4);

    auto load_stage = [&](int kt, int buf) {
        const int kb = kt * BK;
        uint32_t dA = sA0 + (uint32_t)buf * A_STAGE + soff;
        uint32_t dB = sB0 + (uint32_t)buf * B_STAGE + soff;
#pragma unroll
        for (int r = 0; r < 4; r++) {
            CP_ASYNC16(dA + r * 4096, gAp + kb + r * gRstride);
            CP_ASYNC16(dB + r * 4096, gBp + kb + r * gRstride);
        }
    };

    // precomputed ldmatrix offsets (stage-relative); chunk = ks*2 + bit, ks 0..3
    uint32_t aoffs[4][4], boffs[2][4];
#pragma unroll
    for (int mb = 0; mb < 4; mb++) {
        int row = Amb + mb * 16 + i8 + (g & 1) * 8;
#pragma unroll
        for (int ks = 0; ks < 4; ks++)
            aoffs[mb][ks] = tile_off(row, ks * 2 + (g >> 1));
    }
#pragma unroll
    for (int np = 0; np < 2; np++) {
        int row = Bnb + np * 16 + i8 + (g >> 1) * 8;
#pragma unroll
        for (int ks = 0; ks < 4; ks++)
            boffs[np][ks] = tile_off(row, ks * 2 + (g & 1));
    }

    // prologue: fill 2 stages
#pragma unroll
    for (int s = 0; s < NSTAGE - 1; s++) {
        load_stage(s, s);
        CP_COMMIT();
    }

    int buf = 0;            // buffer holding stage kt
    int lbuf = NSTAGE - 1;  // buffer to load next
    for (int kt = 0; kt < KT_ITERS; kt++) {
        CP_WAIT1();         // stage kt resident (<=1 group still in flight)
        __syncthreads();

        int ldkt = kt + NSTAGE - 1;
        if (ldkt < KT_ITERS) load_stage(ldkt, lbuf);
        CP_COMMIT();
        if (++lbuf == NSTAGE) lbuf = 0;

        uint32_t sA = sA0 + (uint32_t)buf * A_STAGE;
        uint32_t sB = sB0 + (uint32_t)buf * B_STAGE;
        if (++buf == NSTAGE) buf = 0;

#pragma unroll
        for (int ks = 0; ks < 4; ks++) {          // four k32 steps per stage
            uint32_t a[4][4], b[2][4];
#pragma unroll
            for (int mb = 0; mb < 4; mb++) LDM_X4(a[mb], sA + aoffs[mb][ks]);
#pragma unroll
            for (int np = 0; np < 2; np++) LDM_X4(b[np], sB + boffs[np][ks]);
#pragma unroll
            for (int mb = 0; mb < 4; mb++)
#pragma unroll
                for (int nb = 0; nb < 4; nb++)
                    MMA_S8(acc[mb][nb], a[mb],
                           b[nb >> 1][(nb & 1) * 2], b[nb >> 1][(nb & 1) * 2 + 1]);
        }
    }

    // ---- epilogue: dequant + bias, float2 stores ----
#pragma unroll
    for (int mb = 0; mb < 4; mb++) {
        int r0 = m0 + Amb + mb * 16 + (lane >> 2);
        float sx0 = sx[r0], sx1 = sx[r0 + 8];
#pragma unroll
        for (int nb = 0; nb < 4; nb++) {
            int c0 = n0 + Bnb + nb * 8 + (lane & 3) * 2;
            float w0 = ws[c0],  w1 = ws[c0 + 1];
            float f0 = bias[c0], f1 = bias[c0 + 1];
            float2 v0, v1;
            v0.x = (float)acc[mb][nb][0] * sx0 * w0 + f0;
            v0.y = (float)acc[mb][nb][1] * sx0 * w1 + f1;
            v1.x = (float)acc[mb][nb][2] * sx1 * w0 + f0;
            v1.y = (float)acc[mb][nb][3] * sx1 * w1 + f1;
            *(float2*)&out[(size_t)r0 * D_DIM + c0]       = v0;
            *(float2*)&out[(size_t)(r0 + 8) * D_DIM + c0] = v1;
        }
    }
}

// ============================================================================
// Host launcher
// ============================================================================
extern "C" void kernel_launch(void* const* d_in, const int* in_sizes, int n_in,
                              void* d_out, int out_size)
{
    const float* x    = (const float*)d_in[0];
    const int*   wi   = (const int*)  d_in[1];
    const float* wsc  = (const float*)d_in[2];
    const float* bias = (const float*)d_in[3];
    float*       out  = (float*)d_out;

    void *pqx = nullptr, *pwq = nullptr, *psx = nullptr;
    cudaGetSymbolAddress(&pqx, g_qx);
    cudaGetSymbolAddress(&pwq, g_wq);
    cudaGetSymbolAddress(&psx, g_sx);

    cudaFuncSetAttribute(gemm_kernel, cudaFuncAttributeMaxDynamicSharedMemorySize,
                         NSTAGE * STAGE_BYTES);

    // 1) fused prep
    prep_kernel<<<8192, 256>>>(x, (const int4*)wi,
                               (signed char*)pqx, (signed char*)pwq, (float*)psx);

    // 2) s8 GEMM + fused dequant
    dim3 grid(D_DIM / BM, D_DIM / BN, 1);
    gemm_kernel<<<grid, THREADS, NSTAGE * STAGE_BYTES>>>(
        (const signed char*)pqx, (const signed char*)pwq,
        (const float*)psx, wsc, bias, out);
}